// round 8
// baseline (speedup 1.0000x reference)
#include <cuda_runtime.h>
#include <cstdint>

// Batched NT-GEMM: C[b,i,j] = sum_d A[b,i,d] * B[b,j,d]
// B=8, M=N=4096, K=128, fp32 in/out.
//
// Phase 1: prepass converts A,B to tf32 (RNA) into __device__ scratch in
// fragment-major layout for mma.sync.m16n8k8.
// Phase 2: 128x256-tile GEMM (512 thr, 2 CTA/SM), cp.async double buffer,
// ld.shared.v4/v2 + mma only in the mainloop.

#define BATCH 8
#define MDIM 4096
#define NDIM 4096
#define KDIM 128

#define TILE_M 128
#define TILE_N 256
#define NCHUNKS 4          // K chunks of 32

// Fragment-major scratch:
// Atf: [b][M128(32)][kt(16)][mt(8)][lane(32)][r(4)]   (16.8 MB)
// Btf: [b][N128(32)][kt(16)][nt(16)][lane(32)][r(2)]  (16.8 MB)
__device__ float g_Atf[(size_t)BATCH * MDIM * KDIM];
__device__ float g_Btf[(size_t)BATCH * NDIM * KDIM];

// Smem per buffer: A 4096 floats [kt4][mt8][lane32][r4]
//                + B 8192 floats [kt4][nt32][lane32][r2]  = 48 KB
#define BUF_FLOATS 12288
#define SMEM_BYTES (2 * BUF_FLOATS * 4)   // 96 KB

__device__ __forceinline__ float f2tf32f(float f) {
    uint32_t u;
    asm("cvt.rna.tf32.f32 %0, %1;" : "=r"(u) : "f"(f));
    return __uint_as_float(u);
}

__device__ __forceinline__ uint32_t smem_u32(const void* p) {
    uint32_t a;
    asm("{ .reg .u64 t; cvta.to.shared.u64 t, %1; cvt.u32.u64 %0, t; }"
        : "=r"(a) : "l"(p));
    return a;
}

// ---------------- Prepass ----------------
__global__ __launch_bounds__(256)
void prep_a_kernel(const float* __restrict__ A) {
    const int id   = blockIdx.x * 256 + threadIdx.x;   // 0 .. 2^20-1
    const int lane = id & 31;
    const int mt   = (id >> 5) & 7;
    const int kt   = (id >> 8) & 15;
    const int M    = (id >> 12) & 31;
    const int b    = id >> 17;

    const int g  = lane >> 2;
    const int tt = lane & 3;
    const int m0 = M * 128 + mt * 16 + g;
    const int k0 = kt * 8 + tt;

    const float* src = A + ((size_t)b * MDIM + m0) * KDIM;
    float4 v;
    v.x = f2tf32f(src[k0]);
    v.y = f2tf32f(src[8 * KDIM + k0]);
    v.z = f2tf32f(src[k0 + 4]);
    v.w = f2tf32f(src[8 * KDIM + k0 + 4]);
    *reinterpret_cast<float4*>(g_Atf + (size_t)id * 4) = v;
}

__global__ __launch_bounds__(256)
void prep_b_kernel(const float* __restrict__ B) {
    const int id   = blockIdx.x * 256 + threadIdx.x;   // 0 .. 2^21-1
    const int lane = id & 31;
    const int nt   = (id >> 5) & 15;
    const int kt   = (id >> 9) & 15;
    const int N    = (id >> 13) & 31;
    const int b    = id >> 18;

    const int g  = lane >> 2;
    const int tt = lane & 3;
    const int n0 = N * 128 + nt * 8 + g;
    const int k0 = kt * 8 + tt;

    const float* src = B + ((size_t)b * NDIM + n0) * KDIM;
    float2 v;
    v.x = f2tf32f(src[k0]);
    v.y = f2tf32f(src[k0 + 4]);
    *reinterpret_cast<float2*>(g_Btf + (size_t)id * 2) = v;
}

// ---------------- Main GEMM: 128x256 tile, 512 threads ----------------
__global__ __launch_bounds__(512, 2)
void bmm_tf32_frag_kernel(float* __restrict__ C) {
    extern __shared__ float sm[];
    const uint32_t smem_base = smem_u32(sm);

    const int tid  = threadIdx.x;
    const int lane = tid & 31;
    const int wid  = tid >> 5;           // 0..15
    const int g    = lane >> 2;
    const int tt   = lane & 3;

    const int b  = blockIdx.z;
    const int by = blockIdx.y;           // M128 tile (0..31)
    const int bx = blockIdx.x;           // N256 tile (0..15)

    const float* srcA  = g_Atf + (size_t)((b * 32 + by) * 16) * 1024;
    const float* srcB0 = g_Btf + (size_t)((b * 32 + bx * 2) * 16) * 1024;
    const float* srcB1 = srcB0 + 16384;
    float* Cb = C + (size_t)b * MDIM * NDIM;

    const int mband = wid >> 3;          // 0..1  (64-row band)
    const int nband = wid & 7;           // 0..7  (32-col band)

    float acc[4][4][4];
    #pragma unroll
    for (int i = 0; i < 4; i++)
        #pragma unroll
        for (int j = 0; j < 4; j++)
            #pragma unroll
            for (int r = 0; r < 4; r++)
                acc[i][j][r] = 0.0f;

    // Prefetch chunk c into buffer buf.
    // A: 1024 float4 contiguous -> contiguous.
    // B: per source block q (0,1): [ktl4][1024 floats] -> smem
    //    [ktl][q*4096B + inner], interleaving the two N128 blocks per ktl.
    auto prefetch = [&](int buf, int c) {
        const uint32_t da = smem_base + (uint32_t)buf * (BUF_FLOATS * 4);
        const uint32_t db = da + 16384;                 // B region (bytes)
        const float* ca = srcA + c * 4096;
        #pragma unroll
        for (int i = 0; i < 2; i++) {
            const int o = tid + i * 512;                // float4 idx 0..1023
            asm volatile("cp.async.cg.shared.global [%0], [%1], 16;"
                         :: "r"(da + (uint32_t)o * 16), "l"(ca + o * 4));
        }
        const float* cb0 = srcB0 + c * 4096;
        const float* cb1 = srcB1 + c * 4096;
        #pragma unroll
        for (int i = 0; i < 2; i++) {
            const int o = tid + i * 512;                // float4 idx 0..1023
            const int ktl = o >> 8;
            const int in4 = o & 255;
            const uint32_t d0 = db + (uint32_t)(ktl * 8192 + in4 * 16);
            asm volatile("cp.async.cg.shared.global [%0], [%1], 16;"
                         :: "r"(d0), "l"(cb0 + o * 4));
            asm volatile("cp.async.cg.shared.global [%0], [%1], 16;"
                         :: "r"(d0 + 4096), "l"(cb1 + o * 4));
        }
    };

    prefetch(0, 0);
    asm volatile("cp.async.commit_group;" ::: "memory");
    prefetch(1, 1);
    asm volatile("cp.async.commit_group;" ::: "memory");

    #pragma unroll
    for (int ch = 0; ch < NCHUNKS; ch++) {
        if (ch < NCHUNKS - 1)
            asm volatile("cp.async.wait_group 1;" ::: "memory");
        else
            asm volatile("cp.async.wait_group 0;" ::: "memory");
        __syncthreads();

        const float* As = sm + (ch & 1) * BUF_FLOATS;   // [kt][mt8][lane][4]
        const float* Bs = As + 4096;                    // [kt][nt32][lane][2]

        #pragma unroll
        for (int kt = 0; kt < 4; kt++) {
            uint32_t a[4][4], bf[4][2];
            #pragma unroll
            for (int i = 0; i < 4; i++) {
                const float* p = As + ((kt * 8 + mband * 4 + i) * 32 + lane) * 4;
                asm volatile("ld.shared.v4.b32 {%0,%1,%2,%3}, [%4];"
                             : "=r"(a[i][0]), "=r"(a[i][1]),
                               "=r"(a[i][2]), "=r"(a[i][3])
                             : "l"(p));
            }
            #pragma unroll
            for (int j = 0; j < 4; j++) {
                const float* p = Bs + ((kt * 32 + nband * 4 + j) * 32 + lane) * 2;
                asm volatile("ld.shared.v2.b32 {%0,%1}, [%2];"
                             : "=r"(bf[j][0]), "=r"(bf[j][1])
                             : "l"(p));
            }
            #pragma unroll
            for (int i = 0; i < 4; i++)
                #pragma unroll
                for (int j = 0; j < 4; j++) {
                    asm volatile(
                        "mma.sync.aligned.m16n8k8.row.col.f32.tf32.tf32.f32 "
                        "{%0,%1,%2,%3}, {%4,%5,%6,%7}, {%8,%9}, {%0,%1,%2,%3};"
                        : "+f"(acc[i][j][0]), "+f"(acc[i][j][1]),
                          "+f"(acc[i][j][2]), "+f"(acc[i][j][3])
                        : "r"(a[i][0]), "r"(a[i][1]),
                          "r"(a[i][2]), "r"(a[i][3]),
                          "r"(bf[j][0]), "r"(bf[j][1]));
                }
        }

        if (ch + 2 < NCHUNKS) {
            __syncthreads();
            prefetch(ch & 1, ch + 2);
            asm volatile("cp.async.commit_group;" ::: "memory");
        }
    }

    // Epilogue
    const int mBase = by * TILE_M;
    const int nBase = bx * TILE_N;
    #pragma unroll
    for (int i = 0; i < 4; i++) {
        const int row0 = mBase + mband * 64 + i * 16 + g;
        #pragma unroll
        for (int j = 0; j < 4; j++) {
            const int col = nBase + nband * 32 + j * 8 + tt * 2;
            float2 lo = make_float2(acc[i][j][0], acc[i][j][1]);
            float2 hi = make_float2(acc[i][j][2], acc[i][j][3]);
            *reinterpret_cast<float2*>(Cb + (size_t)row0 * NDIM + col) = lo;
            *reinterpret_cast<float2*>(Cb + (size_t)(row0 + 8) * NDIM + col) = hi;
        }
    }
}

extern "C" void kernel_launch(void* const* d_in, const int* in_sizes, int n_in,
                              void* d_out, int out_size) {
    const float* A = (const float*)d_in[0];
    const float* B = (const float*)d_in[1];
    float* C = (float*)d_out;

    cudaFuncSetAttribute(bmm_tf32_frag_kernel,
                         cudaFuncAttributeMaxDynamicSharedMemorySize, SMEM_BYTES);

    prep_a_kernel<<<4096, 256>>>(A);     // 2^20 threads
    prep_b_kernel<<<8192, 256>>>(B);     // 2^21 threads

    dim3 grid(NDIM / TILE_N, MDIM / TILE_M, BATCH);  // 16 x 32 x 8 = 4096
    bmm_tf32_frag_kernel<<<grid, 512, SMEM_BYTES>>>(C);
}

// round 9
// speedup vs baseline: 3.6904x; 3.6904x over previous
#include <cuda_runtime.h>
#include <cstdint>

// Batched NT-GEMM: C[b,i,j] = sum_d A[b,i,d] * B[b,j,d]
// B=8, M=N=4096, K=128, fp32 in/out.
//
// Phase 1: prepass converts A,B to tf32 (RNA) into __device__ scratch in
// fragment-major layout for mma.sync.m16n8k8.
// Phase 2: 128x128-tile GEMM (256 thr, 2 CTA/SM), cp.async double buffer,
// ld.shared.v4/v2 + mma only; fragment loads double-buffered in registers
// so MMAs of step kt overlap the LDS of step kt+1.

#define BATCH 8
#define MDIM 4096
#define NDIM 4096
#define KDIM 128

#define TILE_M 128
#define TILE_N 128
#define NCHUNKS 4          // K chunks of 32 (4 kt-groups of 8)

// Fragment-major scratch:
// Atf: [b][M128(32)][kt(16)][mt(8)][lane(32)][r(4)]   (16.8 MB)
// Btf: [b][N128(32)][kt(16)][nt(16)][lane(32)][r(2)]  (16.8 MB)
__device__ float g_Atf[(size_t)BATCH * MDIM * KDIM];
__device__ float g_Btf[(size_t)BATCH * NDIM * KDIM];

// Smem per buffer: A 4096 floats [kt4][mt8][lane32][r4], B 4096 floats
// [kt4][nt16][lane32][r2].  2 buffers x 32KB = 64KB.
#define BUF_FLOATS 8192
#define SMEM_BYTES (2 * BUF_FLOATS * 4)

__device__ __forceinline__ float f2tf32f(float f) {
    uint32_t u;
    asm("cvt.rna.tf32.f32 %0, %1;" : "=r"(u) : "f"(f));
    return __uint_as_float(u);
}

__device__ __forceinline__ uint32_t smem_u32(const void* p) {
    uint32_t a;
    asm("{ .reg .u64 t; cvta.to.shared.u64 t, %1; cvt.u32.u64 %0, t; }"
        : "=r"(a) : "l"(p));
    return a;
}

// ---------------- Prepass ----------------
__global__ __launch_bounds__(256)
void prep_a_kernel(const float* __restrict__ A) {
    const int id   = blockIdx.x * 256 + threadIdx.x;   // 0 .. 2^20-1
    const int lane = id & 31;
    const int mt   = (id >> 5) & 7;
    const int kt   = (id >> 8) & 15;
    const int M    = (id >> 12) & 31;
    const int b    = id >> 17;

    const int g  = lane >> 2;
    const int tt = lane & 3;
    const int m0 = M * 128 + mt * 16 + g;
    const int k0 = kt * 8 + tt;

    const float* src = A + ((size_t)b * MDIM + m0) * KDIM;
    float4 v;
    v.x = f2tf32f(src[k0]);
    v.y = f2tf32f(src[8 * KDIM + k0]);
    v.z = f2tf32f(src[k0 + 4]);
    v.w = f2tf32f(src[8 * KDIM + k0 + 4]);
    *reinterpret_cast<float4*>(g_Atf + (size_t)id * 4) = v;
}

__global__ __launch_bounds__(256)
void prep_b_kernel(const float* __restrict__ B) {
    const int id   = blockIdx.x * 256 + threadIdx.x;   // 0 .. 2^21-1
    const int lane = id & 31;
    const int nt   = (id >> 5) & 15;
    const int kt   = (id >> 9) & 15;
    const int N    = (id >> 13) & 31;
    const int b    = id >> 18;

    const int g  = lane >> 2;
    const int tt = lane & 3;
    const int n0 = N * 128 + nt * 8 + g;
    const int k0 = kt * 8 + tt;

    const float* src = B + ((size_t)b * NDIM + n0) * KDIM;
    float2 v;
    v.x = f2tf32f(src[k0]);
    v.y = f2tf32f(src[k0 + 4]);
    *reinterpret_cast<float2*>(g_Btf + (size_t)id * 2) = v;
}

// ---------------- Main GEMM ----------------
__global__ __launch_bounds__(256, 2)
void bmm_tf32_frag_kernel(float* __restrict__ C) {
    extern __shared__ float sm[];
    const uint32_t smem_base = smem_u32(sm);

    const int tid  = threadIdx.x;
    const int lane = tid & 31;
    const int wid  = tid >> 5;
    const int g    = lane >> 2;
    const int tt   = lane & 3;

    const int b  = blockIdx.z;
    const int by = blockIdx.y;          // M128 tile
    const int bx = blockIdx.x;          // N128 tile

    const float* srcA = g_Atf + (size_t)((b * 32 + by) * 16) * 1024;
    const float* srcB = g_Btf + (size_t)((b * 32 + bx) * 16) * 1024;
    float* Cb = C + (size_t)b * MDIM * NDIM;

    const int mband = wid >> 2;         // 0..1
    const int nband = wid & 3;          // 0..3

    float acc[4][4][4];
    #pragma unroll
    for (int i = 0; i < 4; i++)
        #pragma unroll
        for (int j = 0; j < 4; j++)
            #pragma unroll
            for (int r = 0; r < 4; r++)
                acc[i][j][r] = 0.0f;

    auto prefetch = [&](int buf, int c) {
        const float* ca = srcA + c * 4096;
        const float* cb = srcB + c * 4096;
        const uint32_t da = smem_base + (uint32_t)buf * (BUF_FLOATS * 4);
        const uint32_t db = da + 16384;
        #pragma unroll
        for (int i = 0; i < 4; i++) {
            const int o = tid + i * 256;      // 16B chunk index
            asm volatile("cp.async.cg.shared.global [%0], [%1], 16;"
                         :: "r"(da + (uint32_t)o * 16), "l"(ca + o * 4));
            asm volatile("cp.async.cg.shared.global [%0], [%1], 16;"
                         :: "r"(db + (uint32_t)o * 16), "l"(cb + o * 4));
        }
    };

    prefetch(0, 0);
    asm volatile("cp.async.commit_group;" ::: "memory");
    prefetch(1, 1);
    asm volatile("cp.async.commit_group;" ::: "memory");

    // Register-double-buffered fragments
    uint32_t a[2][4][4], bf[2][4][2];

    #pragma unroll
    for (int ch = 0; ch < NCHUNKS; ch++) {
        if (ch < NCHUNKS - 1)
            asm volatile("cp.async.wait_group 1;" ::: "memory");
        else
            asm volatile("cp.async.wait_group 0;" ::: "memory");
        __syncthreads();

        const float* As = sm + (ch & 1) * BUF_FLOATS;   // [kt][mt8][lane][4]
        const float* Bs = As + 4096;                    // [kt][nt16][lane][2]

        // Load kt=0 fragments into slot 0
        #pragma unroll
        for (int i = 0; i < 4; i++) {
            const float* p = As + ((mband * 4 + i) * 32 + lane) * 4;
            asm volatile("ld.shared.v4.b32 {%0,%1,%2,%3}, [%4];"
                         : "=r"(a[0][i][0]), "=r"(a[0][i][1]),
                           "=r"(a[0][i][2]), "=r"(a[0][i][3])
                         : "l"(p));
        }
        #pragma unroll
        for (int j = 0; j < 4; j++) {
            const float* p = Bs + ((nband * 4 + j) * 32 + lane) * 2;
            asm volatile("ld.shared.v2.b32 {%0,%1}, [%2];"
                         : "=r"(bf[0][j][0]), "=r"(bf[0][j][1])
                         : "l"(p));
        }

        #pragma unroll
        for (int kt = 0; kt < 4; kt++) {
            const int cur = kt & 1;
            const int nxt = cur ^ 1;

            // Prefetch next kt's fragments (overlaps with this kt's MMAs)
            if (kt < 3) {
                #pragma unroll
                for (int i = 0; i < 4; i++) {
                    const float* p =
                        As + (((kt + 1) * 8 + mband * 4 + i) * 32 + lane) * 4;
                    asm volatile("ld.shared.v4.b32 {%0,%1,%2,%3}, [%4];"
                                 : "=r"(a[nxt][i][0]), "=r"(a[nxt][i][1]),
                                   "=r"(a[nxt][i][2]), "=r"(a[nxt][i][3])
                                 : "l"(p));
                }
                #pragma unroll
                for (int j = 0; j < 4; j++) {
                    const float* p =
                        Bs + (((kt + 1) * 16 + nband * 4 + j) * 32 + lane) * 2;
                    asm volatile("ld.shared.v2.b32 {%0,%1}, [%2];"
                                 : "=r"(bf[nxt][j][0]), "=r"(bf[nxt][j][1])
                                 : "l"(p));
                }
            }

            #pragma unroll
            for (int i = 0; i < 4; i++)
                #pragma unroll
                for (int j = 0; j < 4; j++) {
                    asm volatile(
                        "mma.sync.aligned.m16n8k8.row.col.f32.tf32.tf32.f32 "
                        "{%0,%1,%2,%3}, {%4,%5,%6,%7}, {%8,%9}, {%0,%1,%2,%3};"
                        : "+f"(acc[i][j][0]), "+f"(acc[i][j][1]),
                          "+f"(acc[i][j][2]), "+f"(acc[i][j][3])
                        : "r"(a[cur][i][0]), "r"(a[cur][i][1]),
                          "r"(a[cur][i][2]), "r"(a[cur][i][3]),
                          "r"(bf[cur][j][0]), "r"(bf[cur][j][1]));
                }
        }

        if (ch + 2 < NCHUNKS) {
            __syncthreads();
            prefetch(ch & 1, ch + 2);
            asm volatile("cp.async.commit_group;" ::: "memory");
        }
    }

    // Epilogue
    const int mBase = by * TILE_M;
    const int nBase = bx * TILE_N;
    #pragma unroll
    for (int i = 0; i < 4; i++) {
        const int row0 = mBase + mband * 64 + i * 16 + g;
        #pragma unroll
        for (int j = 0; j < 4; j++) {
            const int col = nBase + nband * 32 + j * 8 + tt * 2;
            float2 lo = make_float2(acc[i][j][0], acc[i][j][1]);
            float2 hi = make_float2(acc[i][j][2], acc[i][j][3]);
            *reinterpret_cast<float2*>(Cb + (size_t)row0 * NDIM + col) = lo;
            *reinterpret_cast<float2*>(Cb + (size_t)(row0 + 8) * NDIM + col) = hi;
        }
    }
}

extern "C" void kernel_launch(void* const* d_in, const int* in_sizes, int n_in,
                              void* d_out, int out_size) {
    const float* A = (const float*)d_in[0];
    const float* B = (const float*)d_in[1];
    float* C = (float*)d_out;

    cudaFuncSetAttribute(bmm_tf32_frag_kernel,
                         cudaFuncAttributeMaxDynamicSharedMemorySize, SMEM_BYTES);

    prep_a_kernel<<<4096, 256>>>(A);     // 2^20 threads
    prep_b_kernel<<<8192, 256>>>(B);     // 2^21 threads

    dim3 grid(NDIM / TILE_N, MDIM / TILE_M, BATCH);  // 32 x 32 x 8
    bmm_tf32_frag_kernel<<<grid, 256, SMEM_BYTES>>>(C);
}